// round 16
// baseline (speedup 1.0000x reference)
#include <cuda_runtime.h>
#include <cuda_fp16.h>
#include <cstdint>

#define MAXE 400000
#define MAXN 25000

// ---------------------------------------------------------------------------
__device__ __half g_h1[(size_t)MAXE * 384];   // GEMM1 output (fp16)
__device__ __half g_B[(size_t)MAXE * 384];    // LN+SiLU output (fp16)
__device__ __half g_ang[(size_t)MAXE * 64];   // angle-X rows (fp16)
__device__ __half g_W[253952];
__device__ float g_vb[384];
__device__ unsigned char g_mask[MAXE];
__device__ int g_last;

#define OFF_IW1 0         // 384 x 384
#define OFF_IW2 147456    // 128 x 384
#define OFF_MW1 196608    // 128 x 320
#define OFF_MW2 237568    // 128 x 128

// ---------------------------------------------------------------------------
static __device__ __forceinline__ uint32_t smem_u32(const void* p) {
    uint32_t a;
    asm("{ .reg .u64 t; cvta.to.shared.u64 t, %1; cvt.u32.u64 %0, t; }" : "=r"(a) : "l"(p));
    return a;
}
static __device__ __forceinline__ void cp_async16(uint32_t s, const void* g) {
    asm volatile("cp.async.cg.shared.global [%0], [%1], 16;" :: "r"(s), "l"(g));
}
static __device__ __forceinline__ void cp_commit() {
    asm volatile("cp.async.commit_group;" ::: "memory");
}
template <int N>
static __device__ __forceinline__ void cp_wait() {
    asm volatile("cp.async.wait_group %0;" :: "n"(N) : "memory");
}
static __device__ __forceinline__ void ldsm4(uint32_t* r, uint32_t a) {
    asm volatile("ldmatrix.sync.aligned.m8n8.x4.shared.b16 {%0,%1,%2,%3}, [%4];"
                 : "=r"(r[0]), "=r"(r[1]), "=r"(r[2]), "=r"(r[3]) : "r"(a));
}
static __device__ __forceinline__ void mma16816(float* d, const uint32_t* a, const uint32_t* b) {
    asm volatile(
        "mma.sync.aligned.m16n8k16.row.col.f32.f16.f16.f32 "
        "{%0,%1,%2,%3}, {%4,%5,%6,%7}, {%8,%9}, {%0,%1,%2,%3};"
        : "+f"(d[0]), "+f"(d[1]), "+f"(d[2]), "+f"(d[3])
        : "r"(a[0]), "r"(a[1]), "r"(a[2]), "r"(a[3]), "r"(b[0]), "r"(b[1]));
}

static __device__ __forceinline__ uint32_t packh2(float a, float b) {
    __half2 t = __floats2half2_rn(a, b);
    return *reinterpret_cast<uint32_t*>(&t);
}
static __device__ __forceinline__ uint2 f4h4(float4 v) {
    uint2 r;
    r.x = packh2(v.x, v.y);
    r.y = packh2(v.z, v.w);
    return r;
}

// ---------------------------------------------------------------------------
__global__ __launch_bounds__(256) void k_init(float* __restrict__ node, int n)
{
    int i = blockIdx.x * 256 + threadIdx.x;
    if (i < n) node[i] = 0.f;
}

__global__ __launch_bounds__(256) void k_mask(const int* __restrict__ src,
                                              const int* __restrict__ dst, int E)
{
    int e = blockIdx.x * 256 + threadIdx.x;
    if (e == 0) g_last = -1;
    if (e >= E) return;
    bool m = false;
    if (e + 1 < E)
        m = (src[e] == src[e + 1]) && (src[e] != dst[e]) && (src[e + 1] != dst[e + 1]);
    g_mask[e] = m ? 1 : 0;
    if (m) atomicMax(&g_last, e);
}

__global__ __launch_bounds__(256) void k_split(const float* __restrict__ w,
                                               __half* __restrict__ out, int n)
{
    int i = blockIdx.x * 256 + threadIdx.x;
    if (i < n) out[i] = __float2half_rn(w[i]);
}

// fold angle w2/b2 into iw1 seg5 (cols 320..383 of the fp16 iw1 copy)
__global__ __launch_bounds__(256) void k_wtrans(const float* __restrict__ iw1,
                                                const float* __restrict__ w2,
                                                const float* __restrict__ b2)
{
    int t = blockIdx.x * 256 + threadIdx.x;
    if (t >= 384 * 64) return;
    int n = t >> 6, j = t & 63;
    const float* wr = iw1 + (size_t)n * 384 + 320;
    float acc = 0.f;
    #pragma unroll 8
    for (int o = 0; o < 64; o++) acc = fmaf(wr[o], w2[o * 64 + j], acc);
    g_W[(size_t)n * 384 + 320 + j] = __float2half_rn(acc);
    if (j == 0) {
        float vv = 0.f;
        #pragma unroll 8
        for (int o = 0; o < 64; o++) vv = fmaf(wr[o], b2[o], vv);
        g_vb[n] = vv;
    }
}

// angleX: X = silu(ln(c*w1+b1)) -> g_ang [E,64] fp16 (zeros off-mask)
__global__ __launch_bounds__(128) void k_angleX(const float* __restrict__ ev,
                                                const float* __restrict__ w1,
                                                const float* __restrict__ b1,
                                                const float* __restrict__ g,
                                                const float* __restrict__ bn, int E)
{
    __shared__ float sv[4 * 64];
    if (threadIdx.x < 64) {
        int i = threadIdx.x;
        sv[i] = w1[i]; sv[64 + i] = b1[i]; sv[128 + i] = g[i]; sv[192 + i] = bn[i];
    }
    __syncthreads();
    int e = blockIdx.x * 128 + threadIdx.x;
    if (e >= E) return;
    int last = g_last;
    bool m0 = (g_mask[e] != 0) && (e != last);
    uint2* o = (uint2*)(g_ang + (size_t)e * 64);
    if (!m0) {
        uint2 z = make_uint2(0u, 0u);
        #pragma unroll
        for (int n = 0; n < 16; n++) o[n] = z;
        return;
    }
    float c = 0.f;
    if (e + 1 < E && (g_mask[e + 1] != 0) && (e + 1 != last)) {
        float ax = ev[3 * e],       ay = ev[3 * e + 1],       az = ev[3 * e + 2];
        float bx = ev[3 * (e + 1)], by = ev[3 * (e + 1) + 1], bz = ev[3 * (e + 1) + 2];
        float ra = rsqrtf(ax * ax + ay * ay + az * az);
        float rb = rsqrtf(bx * bx + by * by + bz * bz);
        c = (ax * bx + ay * by + az * bz) * ra * rb;
    }
    float x[64];
    float s = 0.f;
    #pragma unroll
    for (int j = 0; j < 64; j++) { x[j] = fmaf(c, sv[j], sv[64 + j]); s += x[j]; }
    float mean = s * (1.f / 64.f);
    float var = 0.f;
    #pragma unroll
    for (int j = 0; j < 64; j++) { float d = x[j] - mean; var = fmaf(d, d, var); }
    var *= (1.f / 64.f);
    float rs = rsqrtf(var + 1e-6f);
    #pragma unroll
    for (int j = 0; j < 64; j++) {
        float t = (x[j] - mean) * rs * sv[128 + j] + sv[192 + j];
        x[j] = t / (1.f + expf(-t));
    }
    #pragma unroll
    for (int n = 0; n < 16; n++) {
        float4 v = make_float4(x[4 * n], x[4 * n + 1], x[4 * n + 2], x[4 * n + 3]);
        o[n] = f4h4(v);
    }
}

// LayerNorm + SiLU, fp16 in -> fp16 out, rows [M, D]
template <int D>
__global__ __launch_bounds__(256) void ln_silu_hh(const __half* __restrict__ X,
                                                  const float* __restrict__ g,
                                                  const float* __restrict__ b,
                                                  __half* __restrict__ O, int M)
{
    int row = blockIdx.x * 8 + (threadIdx.x >> 5);
    int lane = threadIdx.x & 31;
    if (row >= M) return;
    const __half* x = X + (size_t)row * D;
    constexpr int Cc = D / 32;
    float v[Cc];
    float s = 0.f, s2 = 0.f;
    #pragma unroll
    for (int c = 0; c < Cc; c++) {
        v[c] = __half2float(x[c * 32 + lane]);
        s += v[c];
        s2 = fmaf(v[c], v[c], s2);
    }
    #pragma unroll
    for (int o = 16; o; o >>= 1) {
        s += __shfl_xor_sync(0xffffffffu, s, o);
        s2 += __shfl_xor_sync(0xffffffffu, s2, o);
    }
    float mean = s * (1.f / D);
    float var = s2 * (1.f / D) - mean * mean;
    float rs = rsqrtf(var + 1e-6f);
    __half* hr = O + (size_t)row * D;
    #pragma unroll
    for (int c = 0; c < Cc; c++) {
        float t = (v[c] - mean) * rs * g[c * 32 + lane] + b[c * 32 + lane];
        t = t / (1.f + expf(-t));
        hr[c * 32 + lane] = __float2half_rn(t);
    }
}

// ---------------------------------------------------------------------------
// Single-pass fp16 mma.sync GEMM (fp32 accum). BM=128, BN=128, BK=64,
// 256 threads (8 warps 4Mx2N), double-buffered {A, W} stages, 2 CTAs/SM.
// ATOMIC: scatter-add rows into C[dstIdx[row]].
// FUSE_LN: LN+SiLU epilogue (Nn==128, grid.x==1).
// GATHER: merge-block A gather from node/el (Kseg=320).
// MASKV: add g_vb[col] to masked rows (folded angle b2; GEMM1).
// FUSE2: second in-CTA GEMM on LN rows -> edge (merge block).
// G1: inv-block A gather (Kseg=384, 6 chunks: atom[src]|atom[dst]|el[e]|
//     atom[dst_s]|el[e+1]|angle-buf), masked rows zeroed in-loader.
// OUTH: epilogue writes fp16 into OutB [row, Nn] instead of fp32 C.
#define SM_STRIDE 144
#define A_TILE (128 * SM_STRIDE)            // 18432
#define SM_STAGE (2 * A_TILE)               // 36864
#define SMEM_BYTES (2 * SM_STAGE)           // 73728

template <int ATOMIC, int FUSE_LN, int GATHER, int MASKV, int FUSE2, int G1, int OUTH>
__global__ __launch_bounds__(256, 2) void gemm_mma(const __half* __restrict__ A,
                                                   const __half* __restrict__ W,
                                                   const float* __restrict__ bias,
                                                   float* __restrict__ C, int Nn, int Kseg,
                                                   const int* __restrict__ dstIdx,
                                                   const float* __restrict__ lng,
                                                   const float* __restrict__ lnb,
                                                   __half* __restrict__ OutB,
                                                   const int* __restrict__ srcIdx,
                                                   const float* __restrict__ elP,
                                                   const float* __restrict__ nodeP,
                                                   const float* __restrict__ atomP,
                                                   const __half* __restrict__ angP,
                                                   const __half* __restrict__ w2P,
                                                   const float* __restrict__ b2P,
                                                   float* __restrict__ edgeP)
{
    extern __shared__ char smem[];
    __shared__ int s_src[128], s_dst[128], s_dst2[128], s_mask[128];
    __shared__ float s_red[512];
    const uint32_t sb = smem_u32(smem);
    const int tid = threadIdx.x;
    const int lane = tid & 31, wid = tid >> 5;
    const int warp_m = wid & 3, warp_n = wid >> 2;
    const int n0 = blockIdx.x * 128;
    const int m0 = blockIdx.y * 128;
    const int NKC = Kseg >> 6;

    float acc[2][8][4] = {};

    auto load_stage = [&](int kc, int s) {
        int k0 = kc << 6;
        uint32_t st = sb + s * SM_STAGE;
        #pragma unroll
        for (int i = 0; i < 4; i++) {
            int idx = tid + i * 256;
            int r = idx >> 3, c16 = idx & 7;
            uint32_t so = (uint32_t)(r * SM_STRIDE + c16 * 16);
            cp_async16(st + so,          A + (size_t)(m0 + r) * Kseg + k0 + c16 * 8);
            cp_async16(st + A_TILE + so, W + (size_t)(n0 + r) * Kseg + k0 + c16 * 8);
        }
        cp_commit();
    };

    auto load_W_stage = [&](int kc, int s) {
        int k0 = kc << 6;
        uint32_t st = sb + s * SM_STAGE;
        #pragma unroll
        for (int i = 0; i < 4; i++) {
            int idx = tid + i * 256;
            int r = idx >> 3, c16 = idx & 7;
            uint32_t so = (uint32_t)(r * SM_STRIDE + c16 * 16);
            cp_async16(st + A_TILE + so, W + (size_t)(n0 + r) * Kseg + k0 + c16 * 8);
        }
        cp_commit();
    };

    // merge-block gather (5 chunks, unmasked)
    auto load_A_gather = [&](int kc, int s) {
        int r = tid >> 1;
        int half = tid & 1;
        const float* base;
        if (kc < 2)      base = nodeP + (size_t)s_src[r] * 128 + kc * 64;
        else if (kc < 4) base = nodeP + (size_t)s_dst[r] * 128 + (kc - 2) * 64;
        else             base = elP + (size_t)(m0 + r) * 64;
        base += half * 32;
        char* sh = smem + s * SM_STAGE + r * SM_STRIDE + half * 64;
        #pragma unroll
        for (int i = 0; i < 8; i++) {
            float4 v = ((const float4*)base)[i];
            *(uint2*)(sh + i * 8) = f4h4(v);
        }
    };

    // inv-block gather (6 chunks, masked)
    auto load_A_gather1 = [&](int kc, int s) {
        int r = tid >> 1;
        int half = tid & 1;
        char* sh = smem + s * SM_STAGE + r * SM_STRIDE + half * 64;
        if (kc == 5) {
            const uint4* ap = (const uint4*)(angP + (size_t)(m0 + r) * 64 + half * 32);
            #pragma unroll
            for (int i = 0; i < 4; i++) *(uint4*)(sh + i * 16) = ap[i];
            return;
        }
        if (!s_mask[r]) {
            uint2 z = make_uint2(0u, 0u);
            #pragma unroll
            for (int i = 0; i < 8; i++) *(uint2*)(sh + i * 8) = z;
            return;
        }
        const float* base;
        if (kc == 0)      base = atomP + (size_t)s_src[r] * 64;
        else if (kc == 1) base = atomP + (size_t)s_dst[r] * 64;
        else if (kc == 2) base = elP + (size_t)(m0 + r) * 64;
        else if (kc == 3) base = atomP + (size_t)s_dst2[r] * 64;
        else              base = elP + (size_t)(m0 + r + 1) * 64;
        base += half * 32;
        #pragma unroll
        for (int i = 0; i < 8; i++) {
            float4 v = ((const float4*)base)[i];
            *(uint2*)(sh + i * 8) = f4h4(v);
        }
    };

    auto do_pass = [&](uint32_t sa, uint32_t sw, float (*ac)[8][4]) {
        int arow = warp_m * 32 + (lane & 15);
        uint32_t a_ko = (uint32_t)((lane >> 4) * 16);
        int nrow = warp_n * 64 + ((lane >> 4) & 1) * 8 + (lane & 7);
        uint32_t b_ko = (uint32_t)(((lane >> 3) & 1) * 16);
        #pragma unroll
        for (int kk = 0; kk < 4; kk++) {
            uint32_t kb = (uint32_t)(kk * 32);
            uint32_t af[2][4];
            ldsm4(af[0], sa + arow * SM_STRIDE + kb + a_ko);
            ldsm4(af[1], sa + (arow + 16) * SM_STRIDE + kb + a_ko);
            uint32_t bf[8][2];
            #pragma unroll
            for (int in4 = 0; in4 < 4; in4++) {
                uint32_t q[4];
                ldsm4(q, sw + (nrow + in4 * 16) * SM_STRIDE + kb + b_ko);
                bf[in4 * 2][0] = q[0]; bf[in4 * 2][1] = q[1];
                bf[in4 * 2 + 1][0] = q[2]; bf[in4 * 2 + 1][1] = q[3];
            }
            #pragma unroll
            for (int im = 0; im < 2; im++)
                #pragma unroll
                for (int jn = 0; jn < 8; jn++)
                    mma16816(ac[im][jn], af[im], bf[jn]);
        }
    };

    if (GATHER || G1) {
        if (tid < 128) {
            int e = m0 + tid;
            s_src[tid] = srcIdx[e];
            s_dst[tid] = dstIdx[e];
            if (G1) {
                bool mk = (g_mask[e] != 0) && (e != g_last);
                s_mask[tid] = mk ? 1 : 0;
                s_dst2[tid] = mk ? dstIdx[e + 1] : 0;
            }
        }
        load_W_stage(0, 0);
        for (int kc = 0; kc < NKC; kc++) {
            if (kc + 1 < NKC) { load_W_stage(kc + 1, (kc + 1) & 1); cp_wait<1>(); }
            else              { cp_wait<0>(); }
            __syncthreads();
            if (G1) load_A_gather1(kc, kc & 1);
            else    load_A_gather(kc, kc & 1);
            __syncthreads();
            uint32_t st = sb + (kc & 1) * SM_STAGE;
            do_pass(st, st + A_TILE, acc);
            __syncthreads();
        }
    } else {
        load_stage(0, 0);
        for (int kc = 0; kc < NKC; kc++) {
            if (kc + 1 < NKC) { load_stage(kc + 1, (kc + 1) & 1); cp_wait<1>(); }
            else              { cp_wait<0>(); }
            __syncthreads();
            uint32_t st = sb + (kc & 1) * SM_STAGE;
            do_pass(st, st + A_TILE, acc);
            __syncthreads();
        }
    }

    int tq = lane >> 2, tr = lane & 3;
    int rbase = m0 + warp_m * 32 + tq;
    int cb = n0 + warp_n * 64 + tr * 2;

    if (FUSE_LN) {
        if (FUSE2) {
            #pragma unroll
            for (int i = 0; i < 8; i++) {
                int idx = tid + i * 256;
                int ch = idx >> 10;
                int rem = idx & 1023;
                int r = rem >> 3, c16 = rem & 7;
                cp_async16(sb + SM_STAGE + ch * A_TILE +
                               (uint32_t)(r * SM_STRIDE + c16 * 16),
                           w2P + (size_t)r * 128 + ch * 64 + c16 * 8);
            }
            cp_commit();
        }
        #pragma unroll
        for (int im = 0; im < 2; im++)
            #pragma unroll
            for (int jn = 0; jn < 8; jn++) {
                int col = cb + jn * 8;
                float b0 = bias[col], b1 = bias[col + 1];
                acc[im][jn][0] += b0; acc[im][jn][1] += b1;
                acc[im][jn][2] += b0; acc[im][jn][3] += b1;
            }
        float* ssum = s_red;
        float* ssq  = s_red + 256;
        #pragma unroll
        for (int im = 0; im < 2; im++)
            #pragma unroll
            for (int h = 0; h < 2; h++) {
                float s = 0.f, q = 0.f;
                #pragma unroll
                for (int jn = 0; jn < 8; jn++) {
                    float a = acc[im][jn][2 * h], b = acc[im][jn][2 * h + 1];
                    s += a + b;
                    q = fmaf(a, a, q); q = fmaf(b, b, q);
                }
                s += __shfl_xor_sync(0xffffffffu, s, 1);
                q += __shfl_xor_sync(0xffffffffu, q, 1);
                s += __shfl_xor_sync(0xffffffffu, s, 2);
                q += __shfl_xor_sync(0xffffffffu, q, 2);
                if (tr == 0) {
                    int lr = warp_m * 32 + im * 16 + h * 8 + tq;
                    ssum[lr * 2 + warp_n] = s;
                    ssq[lr * 2 + warp_n] = q;
                }
            }
        __syncthreads();
        #pragma unroll
        for (int im = 0; im < 2; im++)
            #pragma unroll
            for (int h = 0; h < 2; h++) {
                int lr = warp_m * 32 + im * 16 + h * 8 + tq;
                float S = ssum[lr * 2] + ssum[lr * 2 + 1];
                float Q = ssq[lr * 2] + ssq[lr * 2 + 1];
                float mean = S * (1.f / 128.f);
                float var = Q * (1.f / 128.f) - mean * mean;
                float rs = rsqrtf(var + 1e-6f);
                int row = m0 + lr;
                #pragma unroll
                for (int jn = 0; jn < 8; jn++) {
                    int col = cb + jn * 8;
                    float t0 = (acc[im][jn][2 * h] - mean) * rs * lng[col] + lnb[col];
                    float t1 = (acc[im][jn][2 * h + 1] - mean) * rs * lng[col + 1] + lnb[col + 1];
                    t0 = t0 / (1.f + expf(-t0));
                    t1 = t1 / (1.f + expf(-t1));
                    if (FUSE2) {
                        uint32_t off = (uint32_t)((col >> 6) * A_TILE +
                                                  lr * SM_STRIDE + (col & 63) * 2);
                        *(uint32_t*)(smem + off) = packh2(t0, t1);
                    } else {
                        __half* hr = OutB + (size_t)row * 128;
                        *(uint32_t*)(hr + col) = packh2(t0, t1);
                    }
                }
            }
        if (FUSE2) {
            cp_wait<0>();
            __syncthreads();
            float acc2[2][8][4] = {};
            do_pass(sb,          sb + SM_STAGE,          acc2);
            do_pass(sb + A_TILE, sb + SM_STAGE + A_TILE, acc2);
            #pragma unroll
            for (int im = 0; im < 2; im++) {
                int r0 = rbase + im * 16;
                #pragma unroll
                for (int jn = 0; jn < 8; jn++) {
                    int col = cb + jn * 8;
                    float b0 = b2P[col], b1 = b2P[col + 1];
                    float2 v0 = make_float2(acc2[im][jn][0] + b0, acc2[im][jn][1] + b1);
                    float2 v1 = make_float2(acc2[im][jn][2] + b0, acc2[im][jn][3] + b1);
                    *(float2*)(edgeP + (size_t)r0 * 128 + col) = v0;
                    *(float2*)(edgeP + (size_t)(r0 + 8) * 128 + col) = v1;
                }
            }
        }
    } else if (ATOMIC) {
        #pragma unroll
        for (int im = 0; im < 2; im++) {
            int r0 = rbase + im * 16;
            int d0 = dstIdx[r0], d1 = dstIdx[r0 + 8];
            #pragma unroll
            for (int jn = 0; jn < 8; jn++) {
                int col = cb + jn * 8;
                float b0 = bias[col], b1 = bias[col + 1];
                atomicAdd(C + (size_t)d0 * Nn + col,     acc[im][jn][0] + b0);
                atomicAdd(C + (size_t)d0 * Nn + col + 1, acc[im][jn][1] + b1);
                atomicAdd(C + (size_t)d1 * Nn + col,     acc[im][jn][2] + b0);
                atomicAdd(C + (size_t)d1 * Nn + col + 1, acc[im][jn][3] + b1);
            }
        }
    } else {
        const int last = MASKV ? g_last : -1;
        #pragma unroll
        for (int im = 0; im < 2; im++) {
            int r0 = rbase + im * 16;
            float mk0 = 0.f, mk1 = 0.f;
            if (MASKV) {
                mk0 = (g_mask[r0] && r0 != last) ? 1.f : 0.f;
                mk1 = (g_mask[r0 + 8] && (r0 + 8) != last) ? 1.f : 0.f;
            }
            #pragma unroll
            for (int jn = 0; jn < 8; jn++) {
                int col = cb + jn * 8;
                float b0 = bias[col], b1 = bias[col + 1];
                float v00 = acc[im][jn][0] + b0;
                float v01 = acc[im][jn][1] + b1;
                float v10 = acc[im][jn][2] + b0;
                float v11 = acc[im][jn][3] + b1;
                if (MASKV) {
                    float w0 = g_vb[col], w1 = g_vb[col + 1];
                    v00 = fmaf(mk0, w0, v00); v01 = fmaf(mk0, w1, v01);
                    v10 = fmaf(mk1, w0, v10); v11 = fmaf(mk1, w1, v11);
                }
                if (OUTH) {
                    *(uint32_t*)(OutB + (size_t)r0 * Nn + col) = packh2(v00, v01);
                    *(uint32_t*)(OutB + (size_t)(r0 + 8) * Nn + col) = packh2(v10, v11);
                } else {
                    *(float2*)(C + (size_t)r0 * Nn + col) = make_float2(v00, v01);
                    *(float2*)(C + (size_t)(r0 + 8) * Nn + col) = make_float2(v10, v11);
                }
            }
        }
    }
}

// ---------------------------------------------------------------------------
extern "C" void kernel_launch(void* const* d_in, const int* in_sizes, int n_in,
                              void* d_out, int out_size)
{
    const float* atom = (const float*)d_in[0];
    const float* el   = (const float*)d_in[1];
    const float* ev   = (const float*)d_in[2];
    const int* eidx   = (const int*)d_in[3];
    const float* aw1 = (const float*)d_in[4];
    const float* ab1 = (const float*)d_in[5];
    const float* ag  = (const float*)d_in[6];
    const float* abn = (const float*)d_in[7];
    const float* aw2 = (const float*)d_in[8];
    const float* ab2 = (const float*)d_in[9];
    const float* iw1 = (const float*)d_in[10];
    const float* ib1 = (const float*)d_in[11];
    const float* ig  = (const float*)d_in[12];
    const float* ibn = (const float*)d_in[13];
    const float* iw2 = (const float*)d_in[14];
    const float* ib2 = (const float*)d_in[15];
    const float* mw1 = (const float*)d_in[16];
    const float* mb1 = (const float*)d_in[17];
    const float* mg  = (const float*)d_in[18];
    const float* mbn = (const float*)d_in[19];
    const float* mw2 = (const float*)d_in[20];
    const float* mb2 = (const float*)d_in[21];

    int Na = in_sizes[0] / 64;   // 25000
    int E  = in_sizes[2] / 3;    // 400000
    const int* src = eidx;
    const int* dst = eidx + E;
    float* node = (float*)d_out;
    float* edge = node + (size_t)Na * 128;

    __half *h1h, *B, *W, *ang;
    cudaGetSymbolAddress((void**)&h1h, g_h1);
    cudaGetSymbolAddress((void**)&B, g_B);
    cudaGetSymbolAddress((void**)&W, g_W);
    cudaGetSymbolAddress((void**)&ang, g_ang);

    cudaFuncSetAttribute(gemm_mma<0, 0, 0, 1, 0, 1, 1>, cudaFuncAttributeMaxDynamicSharedMemorySize, SMEM_BYTES);
    cudaFuncSetAttribute(gemm_mma<1, 0, 0, 0, 0, 0, 0>, cudaFuncAttributeMaxDynamicSharedMemorySize, SMEM_BYTES);
    cudaFuncSetAttribute(gemm_mma<0, 1, 1, 0, 1, 0, 0>, cudaFuncAttributeMaxDynamicSharedMemorySize, SMEM_BYTES);

    int MT = E / 128;  // 3125

    k_mask<<<(E + 255) / 256, 256>>>(src, dst, E);
    k_angleX<<<(E + 127) / 128, 128>>>(ev, aw1, ab1, ag, abn, E);
    k_split<<<(147456 + 255) / 256, 256>>>(iw1, W + OFF_IW1, 147456);
    k_wtrans<<<(384 * 64 + 255) / 256, 256>>>(iw1, aw2, ab2);
    k_init<<<(Na * 128 + 255) / 256, 256>>>(node, Na * 128);
    k_split<<<(49152 + 255) / 256, 256>>>(iw2, W + OFF_IW2, 49152);
    k_split<<<(40960 + 255) / 256, 256>>>(mw1, W + OFF_MW1, 40960);
    k_split<<<(16384 + 255) / 256, 256>>>(mw2, W + OFF_MW2, 16384);
    // GEMM1: gathered feat @ iw1' + ib1 (+ masked folded angle-b2) -> h1 fp16
    gemm_mma<0, 0, 0, 1, 0, 1, 1><<<dim3(3, MT), 256, SMEM_BYTES>>>(
        nullptr, W + OFF_IW1, ib1, nullptr, 384, 384, dst, nullptr, nullptr, h1h,
        src, el, nullptr, atom, ang, nullptr, nullptr, nullptr);
    ln_silu_hh<384><<<(E + 7) / 8, 256>>>(h1h, ig, ibn, B, E);
    // GEMM2: silu(ln(h1)) @ iw2 + ib2, scatter-add into node
    gemm_mma<1, 0, 0, 0, 0, 0, 0><<<dim3(1, MT), 256, SMEM_BYTES>>>(
        B, W + OFF_IW2, ib2, node, 128, 384, dst, nullptr, nullptr, nullptr,
        nullptr, nullptr, nullptr, nullptr, nullptr, nullptr, nullptr, nullptr);
    // GEMM3+4 fused: gather cat2 -> @mw1+mb1 -> LN+SiLU (smem) -> @mw2+mb2 -> edge
    gemm_mma<0, 1, 1, 0, 1, 0, 0><<<dim3(1, MT), 256, SMEM_BYTES>>>(
        nullptr, W + OFF_MW1, mb1, nullptr, 128, 320, dst, mg, mbn, nullptr,
        src, el, node, nullptr, nullptr, W + OFF_MW2, mb2, edge);
}

// round 17
// speedup vs baseline: 1.1511x; 1.1511x over previous
#include <cuda_runtime.h>
#include <cuda_fp16.h>
#include <cstdint>

#define MAXE 400000
#define MAXN 25000

// ---------------------------------------------------------------------------
__device__ __half g_A[(size_t)MAXE * 384];    // feat (fp16)
__device__ __half g_h1[(size_t)MAXE * 384];   // GEMM1 output (fp16)
__device__ __half g_B[(size_t)MAXE * 384];    // LN+SiLU output (fp16)
__device__ __half g_W[253952];
__device__ float g_vb[384];
__device__ unsigned char g_mask[MAXE];
__device__ int g_last;

#define OFF_IW1 0         // 384 x 384
#define OFF_IW2 147456    // 128 x 384
#define OFF_MW1 196608    // 128 x 320
#define OFF_MW2 237568    // 128 x 128

// ---------------------------------------------------------------------------
static __device__ __forceinline__ uint32_t smem_u32(const void* p) {
    uint32_t a;
    asm("{ .reg .u64 t; cvta.to.shared.u64 t, %1; cvt.u32.u64 %0, t; }" : "=r"(a) : "l"(p));
    return a;
}
static __device__ __forceinline__ void cp_async16(uint32_t s, const void* g) {
    asm volatile("cp.async.cg.shared.global [%0], [%1], 16;" :: "r"(s), "l"(g));
}
static __device__ __forceinline__ void cp_commit() {
    asm volatile("cp.async.commit_group;" ::: "memory");
}
template <int N>
static __device__ __forceinline__ void cp_wait() {
    asm volatile("cp.async.wait_group %0;" :: "n"(N) : "memory");
}
static __device__ __forceinline__ void ldsm4(uint32_t* r, uint32_t a) {
    asm volatile("ldmatrix.sync.aligned.m8n8.x4.shared.b16 {%0,%1,%2,%3}, [%4];"
                 : "=r"(r[0]), "=r"(r[1]), "=r"(r[2]), "=r"(r[3]) : "r"(a));
}
static __device__ __forceinline__ void mma16816(float* d, const uint32_t* a, const uint32_t* b) {
    asm volatile(
        "mma.sync.aligned.m16n8k16.row.col.f32.f16.f16.f32 "
        "{%0,%1,%2,%3}, {%4,%5,%6,%7}, {%8,%9}, {%0,%1,%2,%3};"
        : "+f"(d[0]), "+f"(d[1]), "+f"(d[2]), "+f"(d[3])
        : "r"(a[0]), "r"(a[1]), "r"(a[2]), "r"(a[3]), "r"(b[0]), "r"(b[1]));
}

static __device__ __forceinline__ uint32_t packh2(float a, float b) {
    __half2 t = __floats2half2_rn(a, b);
    return *reinterpret_cast<uint32_t*>(&t);
}
static __device__ __forceinline__ uint2 f4h4(float4 v) {
    uint2 r;
    r.x = packh2(v.x, v.y);
    r.y = packh2(v.z, v.w);
    return r;
}

// ---------------------------------------------------------------------------
__global__ __launch_bounds__(256) void k_init(float* __restrict__ node, int n)
{
    int i = blockIdx.x * 256 + threadIdx.x;
    if (i < n) node[i] = 0.f;
}

__global__ __launch_bounds__(256) void k_mask(const int* __restrict__ src,
                                              const int* __restrict__ dst, int E)
{
    int e = blockIdx.x * 256 + threadIdx.x;
    if (e == 0) g_last = -1;
    if (e >= E) return;
    bool m = false;
    if (e + 1 < E)
        m = (src[e] == src[e + 1]) && (src[e] != dst[e]) && (src[e + 1] != dst[e + 1]);
    g_mask[e] = m ? 1 : 0;
    if (m) atomicMax(&g_last, e);
}

__global__ __launch_bounds__(256) void k_split(const float* __restrict__ w,
                                               __half* __restrict__ out, int n)
{
    int i = blockIdx.x * 256 + threadIdx.x;
    if (i < n) out[i] = __float2half_rn(w[i]);
}

// fold angle w2/b2 into iw1 seg5 (cols 320..383 of the fp16 iw1 copy)
__global__ __launch_bounds__(256) void k_wtrans(const float* __restrict__ iw1,
                                                const float* __restrict__ w2,
                                                const float* __restrict__ b2)
{
    int t = blockIdx.x * 256 + threadIdx.x;
    if (t >= 384 * 64) return;
    int n = t >> 6, j = t & 63;
    const float* wr = iw1 + (size_t)n * 384 + 320;
    float acc = 0.f;
    #pragma unroll 8
    for (int o = 0; o < 64; o++) acc = fmaf(wr[o], w2[o * 64 + j], acc);
    g_W[(size_t)n * 384 + 320 + j] = __float2half_rn(acc);
    if (j == 0) {
        float vv = 0.f;
        #pragma unroll 8
        for (int o = 0; o < 64; o++) vv = fmaf(wr[o], b2[o], vv);
        g_vb[n] = vv;
    }
}

// feat -> g_A [E,384] fp16, cols 0..319 (angleX fills 320..383)
__global__ __launch_bounds__(256) void k_feat(const float* __restrict__ atom,
                                              const float* __restrict__ el,
                                              const int* __restrict__ src,
                                              const int* __restrict__ dst, int E)
{
    int e = (blockIdx.x * 256 + threadIdx.x) >> 5;
    int lane = threadIdx.x & 31;
    if (e >= E) return;
    bool m = (g_mask[e] != 0) && (e != g_last);
    uint2* o = (uint2*)(g_A + (size_t)e * 384);
    if (!m) {
        uint2 z = make_uint2(0u, 0u);
        o[lane] = z;
        o[lane + 32] = z;
        if (lane < 16) o[lane + 64] = z;
        return;
    }
    int s = src[e], d = dst[e], d2 = dst[e + 1];
    const float4* p0 = (const float4*)(atom + (size_t)s * 64);
    const float4* p1 = (const float4*)(atom + (size_t)d * 64);
    const float4* p2 = (const float4*)(el + (size_t)e * 64);
    const float4* p3 = (const float4*)(atom + (size_t)d2 * 64);
    const float4* p4 = (const float4*)(el + (size_t)(e + 1) * 64);
    float4 v0 = (lane < 16) ? p0[lane] : p1[lane - 16];
    float4 v1 = (lane < 16) ? p2[lane] : p3[lane - 16];
    o[lane] = f4h4(v0);
    o[lane + 32] = f4h4(v1);
    if (lane < 16) o[lane + 64] = f4h4(p4[lane]);
}

// angleX: X = silu(ln(c*w1+b1)) -> g_A cols 320..383 fp16
__global__ __launch_bounds__(128) void k_angleX(const float* __restrict__ ev,
                                                const float* __restrict__ w1,
                                                const float* __restrict__ b1,
                                                const float* __restrict__ g,
                                                const float* __restrict__ bn, int E)
{
    __shared__ float sv[4 * 64];
    if (threadIdx.x < 64) {
        int i = threadIdx.x;
        sv[i] = w1[i]; sv[64 + i] = b1[i]; sv[128 + i] = g[i]; sv[192 + i] = bn[i];
    }
    __syncthreads();
    int e = blockIdx.x * 128 + threadIdx.x;
    if (e >= E) return;
    int last = g_last;
    bool m0 = (g_mask[e] != 0) && (e != last);
    uint2* o = (uint2*)(g_A + (size_t)e * 384 + 320);
    if (!m0) {
        uint2 z = make_uint2(0u, 0u);
        #pragma unroll
        for (int n = 0; n < 16; n++) o[n] = z;
        return;
    }
    float c = 0.f;
    if (e + 1 < E && (g_mask[e + 1] != 0) && (e + 1 != last)) {
        float ax = ev[3 * e],       ay = ev[3 * e + 1],       az = ev[3 * e + 2];
        float bx = ev[3 * (e + 1)], by = ev[3 * (e + 1) + 1], bz = ev[3 * (e + 1) + 2];
        float ra = rsqrtf(ax * ax + ay * ay + az * az);
        float rb = rsqrtf(bx * bx + by * by + bz * bz);
        c = (ax * bx + ay * by + az * bz) * ra * rb;
    }
    float x[64];
    float s = 0.f;
    #pragma unroll
    for (int j = 0; j < 64; j++) { x[j] = fmaf(c, sv[j], sv[64 + j]); s += x[j]; }
    float mean = s * (1.f / 64.f);
    float var = 0.f;
    #pragma unroll
    for (int j = 0; j < 64; j++) { float d = x[j] - mean; var = fmaf(d, d, var); }
    var *= (1.f / 64.f);
    float rs = rsqrtf(var + 1e-6f);
    #pragma unroll
    for (int j = 0; j < 64; j++) {
        float t = (x[j] - mean) * rs * sv[128 + j] + sv[192 + j];
        x[j] = t / (1.f + expf(-t));
    }
    #pragma unroll
    for (int n = 0; n < 16; n++) {
        float4 v = make_float4(x[4 * n], x[4 * n + 1], x[4 * n + 2], x[4 * n + 3]);
        o[n] = f4h4(v);
    }
}

// LayerNorm + SiLU, fp16 in -> fp16 out, rows [M, D]
template <int D>
__global__ __launch_bounds__(256) void ln_silu_hh(const __half* __restrict__ X,
                                                  const float* __restrict__ g,
                                                  const float* __restrict__ b,
                                                  __half* __restrict__ O, int M)
{
    int row = blockIdx.x * 8 + (threadIdx.x >> 5);
    int lane = threadIdx.x & 31;
    if (row >= M) return;
    const __half* x = X + (size_t)row * D;
    constexpr int Cc = D / 32;
    float v[Cc];
    float s = 0.f, s2 = 0.f;
    #pragma unroll
    for (int c = 0; c < Cc; c++) {
        v[c] = __half2float(x[c * 32 + lane]);
        s += v[c];
        s2 = fmaf(v[c], v[c], s2);
    }
    #pragma unroll
    for (int o = 16; o; o >>= 1) {
        s += __shfl_xor_sync(0xffffffffu, s, o);
        s2 += __shfl_xor_sync(0xffffffffu, s2, o);
    }
    float mean = s * (1.f / D);
    float var = s2 * (1.f / D) - mean * mean;
    float rs = rsqrtf(var + 1e-6f);
    __half* hr = O + (size_t)row * D;
    #pragma unroll
    for (int c = 0; c < Cc; c++) {
        float t = (v[c] - mean) * rs * g[c * 32 + lane] + b[c * 32 + lane];
        t = t / (1.f + expf(-t));
        hr[c * 32 + lane] = __float2half_rn(t);
    }
}

// ---------------------------------------------------------------------------
// Single-pass fp16 mma.sync GEMM (fp32 accum). BM=128, BN=128, BK=64,
// 256 threads (8 warps 4Mx2N), double-buffered {A, W} stages, 2 CTAs/SM.
// ATOMIC: scatter-add rows into C[dstIdx[row]].
// FUSE_LN: LN+SiLU epilogue (Nn==128, grid.x==1).
// GATHER: merge-block A gather from node/el (Kseg=320, grid.x==1).
// MASKV: add g_vb[col] to masked rows (folded angle b2; GEMM1).
// FUSE2: second in-CTA GEMM on LN rows -> edge (merge block).
// OUTH: epilogue writes fp16 into OutB [row, Nn] instead of fp32 C.
#define SM_STRIDE 144
#define A_TILE (128 * SM_STRIDE)            // 18432
#define SM_STAGE (2 * A_TILE)               // 36864
#define SMEM_BYTES (2 * SM_STAGE)           // 73728

template <int ATOMIC, int FUSE_LN, int GATHER, int MASKV, int FUSE2, int OUTH>
__global__ __launch_bounds__(256, 2) void gemm_mma(const __half* __restrict__ A,
                                                   const __half* __restrict__ W,
                                                   const float* __restrict__ bias,
                                                   float* __restrict__ C, int Nn, int Kseg,
                                                   const int* __restrict__ dstIdx,
                                                   const float* __restrict__ lng,
                                                   const float* __restrict__ lnb,
                                                   __half* __restrict__ OutB,
                                                   const int* __restrict__ srcIdx,
                                                   const float* __restrict__ elP,
                                                   const float* __restrict__ nodeP,
                                                   const __half* __restrict__ w2P,
                                                   const float* __restrict__ b2P,
                                                   float* __restrict__ edgeP)
{
    extern __shared__ char smem[];
    __shared__ int s_src[128], s_dst[128];
    __shared__ float s_red[512];
    const uint32_t sb = smem_u32(smem);
    const int tid = threadIdx.x;
    const int lane = tid & 31, wid = tid >> 5;
    const int warp_m = wid & 3, warp_n = wid >> 2;
    const int n0 = blockIdx.x * 128;
    const int m0 = blockIdx.y * 128;
    const int NKC = Kseg >> 6;

    float acc[2][8][4] = {};

    auto load_stage = [&](int kc, int s) {
        int k0 = kc << 6;
        uint32_t st = sb + s * SM_STAGE;
        #pragma unroll
        for (int i = 0; i < 4; i++) {
            int idx = tid + i * 256;
            int r = idx >> 3, c16 = idx & 7;
            uint32_t so = (uint32_t)(r * SM_STRIDE + c16 * 16);
            cp_async16(st + so,          A + (size_t)(m0 + r) * Kseg + k0 + c16 * 8);
            cp_async16(st + A_TILE + so, W + (size_t)(n0 + r) * Kseg + k0 + c16 * 8);
        }
        cp_commit();
    };

    auto load_W_stage = [&](int kc, int s) {
        int k0 = kc << 6;
        uint32_t st = sb + s * SM_STAGE;
        #pragma unroll
        for (int i = 0; i < 4; i++) {
            int idx = tid + i * 256;
            int r = idx >> 3, c16 = idx & 7;
            uint32_t so = (uint32_t)(r * SM_STRIDE + c16 * 16);
            cp_async16(st + A_TILE + so, W + (size_t)(n0 + r) * Kseg + k0 + c16 * 8);
        }
        cp_commit();
    };

    auto load_A_gather = [&](int kc, int s) {
        int r = tid >> 1;
        int half = tid & 1;
        const float* base;
        if (kc < 2)      base = nodeP + (size_t)s_src[r] * 128 + kc * 64;
        else if (kc < 4) base = nodeP + (size_t)s_dst[r] * 128 + (kc - 2) * 64;
        else             base = elP + (size_t)(m0 + r) * 64;
        base += half * 32;
        char* sh = smem + s * SM_STAGE + r * SM_STRIDE + half * 64;
        #pragma unroll
        for (int i = 0; i < 8; i++) {
            float4 v = ((const float4*)base)[i];
            *(uint2*)(sh + i * 8) = f4h4(v);
        }
    };

    auto do_pass = [&](uint32_t sa, uint32_t sw, float (*ac)[8][4]) {
        int arow = warp_m * 32 + (lane & 15);
        uint32_t a_ko = (uint32_t)((lane >> 4) * 16);
        int nrow = warp_n * 64 + ((lane >> 4) & 1) * 8 + (lane & 7);
        uint32_t b_ko = (uint32_t)(((lane >> 3) & 1) * 16);
        #pragma unroll
        for (int kk = 0; kk < 4; kk++) {
            uint32_t kb = (uint32_t)(kk * 32);
            uint32_t af[2][4];
            ldsm4(af[0], sa + arow * SM_STRIDE + kb + a_ko);
            ldsm4(af[1], sa + (arow + 16) * SM_STRIDE + kb + a_ko);
            uint32_t bf[8][2];
            #pragma unroll
            for (int in4 = 0; in4 < 4; in4++) {
                uint32_t q[4];
                ldsm4(q, sw + (nrow + in4 * 16) * SM_STRIDE + kb + b_ko);
                bf[in4 * 2][0] = q[0]; bf[in4 * 2][1] = q[1];
                bf[in4 * 2 + 1][0] = q[2]; bf[in4 * 2 + 1][1] = q[3];
            }
            #pragma unroll
            for (int im = 0; im < 2; im++)
                #pragma unroll
                for (int jn = 0; jn < 8; jn++)
                    mma16816(ac[im][jn], af[im], bf[jn]);
        }
    };

    if (GATHER) {
        if (tid < 128) {
            s_src[tid] = srcIdx[m0 + tid];
            s_dst[tid] = dstIdx[m0 + tid];
        }
        load_W_stage(0, 0);
        for (int kc = 0; kc < NKC; kc++) {
            if (kc + 1 < NKC) { load_W_stage(kc + 1, (kc + 1) & 1); cp_wait<1>(); }
            else              { cp_wait<0>(); }
            __syncthreads();
            load_A_gather(kc, kc & 1);
            __syncthreads();
            uint32_t st = sb + (kc & 1) * SM_STAGE;
            do_pass(st, st + A_TILE, acc);
            __syncthreads();
        }
    } else {
        load_stage(0, 0);
        for (int kc = 0; kc < NKC; kc++) {
            if (kc + 1 < NKC) { load_stage(kc + 1, (kc + 1) & 1); cp_wait<1>(); }
            else              { cp_wait<0>(); }
            __syncthreads();
            uint32_t st = sb + (kc & 1) * SM_STAGE;
            do_pass(st, st + A_TILE, acc);
            __syncthreads();
        }
    }

    int tq = lane >> 2, tr = lane & 3;
    int rbase = m0 + warp_m * 32 + tq;
    int cb = n0 + warp_n * 64 + tr * 2;

    if (FUSE_LN) {
        if (FUSE2) {
            #pragma unroll
            for (int i = 0; i < 8; i++) {
                int idx = tid + i * 256;
                int ch = idx >> 10;
                int rem = idx & 1023;
                int r = rem >> 3, c16 = rem & 7;
                cp_async16(sb + SM_STAGE + ch * A_TILE +
                               (uint32_t)(r * SM_STRIDE + c16 * 16),
                           w2P + (size_t)r * 128 + ch * 64 + c16 * 8);
            }
            cp_commit();
        }
        #pragma unroll
        for (int im = 0; im < 2; im++)
            #pragma unroll
            for (int jn = 0; jn < 8; jn++) {
                int col = cb + jn * 8;
                float b0 = bias[col], b1 = bias[col + 1];
                acc[im][jn][0] += b0; acc[im][jn][1] += b1;
                acc[im][jn][2] += b0; acc[im][jn][3] += b1;
            }
        float* ssum = s_red;
        float* ssq  = s_red + 256;
        #pragma unroll
        for (int im = 0; im < 2; im++)
            #pragma unroll
            for (int h = 0; h < 2; h++) {
                float s = 0.f, q = 0.f;
                #pragma unroll
                for (int jn = 0; jn < 8; jn++) {
                    float a = acc[im][jn][2 * h], b = acc[im][jn][2 * h + 1];
                    s += a + b;
                    q = fmaf(a, a, q); q = fmaf(b, b, q);
                }
                s += __shfl_xor_sync(0xffffffffu, s, 1);
                q += __shfl_xor_sync(0xffffffffu, q, 1);
                s += __shfl_xor_sync(0xffffffffu, s, 2);
                q += __shfl_xor_sync(0xffffffffu, q, 2);
                if (tr == 0) {
                    int lr = warp_m * 32 + im * 16 + h * 8 + tq;
                    ssum[lr * 2 + warp_n] = s;
                    ssq[lr * 2 + warp_n] = q;
                }
            }
        __syncthreads();
        #pragma unroll
        for (int im = 0; im < 2; im++)
            #pragma unroll
            for (int h = 0; h < 2; h++) {
                int lr = warp_m * 32 + im * 16 + h * 8 + tq;
                float S = ssum[lr * 2] + ssum[lr * 2 + 1];
                float Q = ssq[lr * 2] + ssq[lr * 2 + 1];
                float mean = S * (1.f / 128.f);
                float var = Q * (1.f / 128.f) - mean * mean;
                float rs = rsqrtf(var + 1e-6f);
                int row = m0 + lr;
                #pragma unroll
                for (int jn = 0; jn < 8; jn++) {
                    int col = cb + jn * 8;
                    float t0 = (acc[im][jn][2 * h] - mean) * rs * lng[col] + lnb[col];
                    float t1 = (acc[im][jn][2 * h + 1] - mean) * rs * lng[col + 1] + lnb[col + 1];
                    t0 = t0 / (1.f + expf(-t0));
                    t1 = t1 / (1.f + expf(-t1));
                    if (FUSE2) {
                        uint32_t off = (uint32_t)((col >> 6) * A_TILE +
                                                  lr * SM_STRIDE + (col & 63) * 2);
                        *(uint32_t*)(smem + off) = packh2(t0, t1);
                    } else {
                        __half* hr = OutB + (size_t)row * 128;
                        *(uint32_t*)(hr + col) = packh2(t0, t1);
                    }
                }
            }
        if (FUSE2) {
            cp_wait<0>();
            __syncthreads();
            float acc2[2][8][4] = {};
            do_pass(sb,          sb + SM_STAGE,          acc2);
            do_pass(sb + A_TILE, sb + SM_STAGE + A_TILE, acc2);
            #pragma unroll
            for (int im = 0; im < 2; im++) {
                int r0 = rbase + im * 16;
                #pragma unroll
                for (int jn = 0; jn < 8; jn++) {
                    int col = cb + jn * 8;
                    float b0 = b2P[col], b1 = b2P[col + 1];
                    float2 v0 = make_float2(acc2[im][jn][0] + b0, acc2[im][jn][1] + b1);
                    float2 v1 = make_float2(acc2[im][jn][2] + b0, acc2[im][jn][3] + b1);
                    *(float2*)(edgeP + (size_t)r0 * 128 + col) = v0;
                    *(float2*)(edgeP + (size_t)(r0 + 8) * 128 + col) = v1;
                }
            }
        }
    } else if (ATOMIC) {
        #pragma unroll
        for (int im = 0; im < 2; im++) {
            int r0 = rbase + im * 16;
            int d0 = dstIdx[r0], d1 = dstIdx[r0 + 8];
            #pragma unroll
            for (int jn = 0; jn < 8; jn++) {
                int col = cb + jn * 8;
                float b0 = bias[col], b1 = bias[col + 1];
                atomicAdd(C + (size_t)d0 * Nn + col,     acc[im][jn][0] + b0);
                atomicAdd(C + (size_t)d0 * Nn + col + 1, acc[im][jn][1] + b1);
                atomicAdd(C + (size_t)d1 * Nn + col,     acc[im][jn][2] + b0);
                atomicAdd(C + (size_t)d1 * Nn + col + 1, acc[im][jn][3] + b1);
            }
        }
    } else {
        const int last = MASKV ? g_last : -1;
        #pragma unroll
        for (int im = 0; im < 2; im++) {
            int r0 = rbase + im * 16;
            float mk0 = 0.f, mk1 = 0.f;
            if (MASKV) {
                mk0 = (g_mask[r0] && r0 != last) ? 1.f : 0.f;
                mk1 = (g_mask[r0 + 8] && (r0 + 8) != last) ? 1.f : 0.f;
            }
            #pragma unroll
            for (int jn = 0; jn < 8; jn++) {
                int col = cb + jn * 8;
                float b0 = bias[col], b1 = bias[col + 1];
                float v00 = acc[im][jn][0] + b0;
                float v01 = acc[im][jn][1] + b1;
                float v10 = acc[im][jn][2] + b0;
                float v11 = acc[im][jn][3] + b1;
                if (MASKV) {
                    float w0 = g_vb[col], w1 = g_vb[col + 1];
                    v00 = fmaf(mk0, w0, v00); v01 = fmaf(mk0, w1, v01);
                    v10 = fmaf(mk1, w0, v10); v11 = fmaf(mk1, w1, v11);
                }
                if (OUTH) {
                    *(uint32_t*)(OutB + (size_t)r0 * Nn + col) = packh2(v00, v01);
                    *(uint32_t*)(OutB + (size_t)(r0 + 8) * Nn + col) = packh2(v10, v11);
                } else {
                    *(float2*)(C + (size_t)r0 * Nn + col) = make_float2(v00, v01);
                    *(float2*)(C + (size_t)(r0 + 8) * Nn + col) = make_float2(v10, v11);
                }
            }
        }
    }
}

// ---------------------------------------------------------------------------
extern "C" void kernel_launch(void* const* d_in, const int* in_sizes, int n_in,
                              void* d_out, int out_size)
{
    const float* atom = (const float*)d_in[0];
    const float* el   = (const float*)d_in[1];
    const float* ev   = (const float*)d_in[2];
    const int* eidx   = (const int*)d_in[3];
    const float* aw1 = (const float*)d_in[4];
    const float* ab1 = (const float*)d_in[5];
    const float* ag  = (const float*)d_in[6];
    const float* abn = (const float*)d_in[7];
    const float* aw2 = (const float*)d_in[8];
    const float* ab2 = (const float*)d_in[9];
    const float* iw1 = (const float*)d_in[10];
    const float* ib1 = (const float*)d_in[11];
    const float* ig  = (const float*)d_in[12];
    const float* ibn = (const float*)d_in[13];
    const float* iw2 = (const float*)d_in[14];
    const float* ib2 = (const float*)d_in[15];
    const float* mw1 = (const float*)d_in[16];
    const float* mb1 = (const float*)d_in[17];
    const float* mg  = (const float*)d_in[18];
    const float* mbn = (const float*)d_in[19];
    const float* mw2 = (const float*)d_in[20];
    const float* mb2 = (const float*)d_in[21];

    int Na = in_sizes[0] / 64;   // 25000
    int E  = in_sizes[2] / 3;    // 400000
    const int* src = eidx;
    const int* dst = eidx + E;
    float* node = (float*)d_out;
    float* edge = node + (size_t)Na * 128;

    __half *A, *h1h, *B, *W;
    cudaGetSymbolAddress((void**)&A, g_A);
    cudaGetSymbolAddress((void**)&h1h, g_h1);
    cudaGetSymbolAddress((void**)&B, g_B);
    cudaGetSymbolAddress((void**)&W, g_W);

    cudaFuncSetAttribute(gemm_mma<0, 0, 0, 1, 0, 1>, cudaFuncAttributeMaxDynamicSharedMemorySize, SMEM_BYTES);
    cudaFuncSetAttribute(gemm_mma<1, 0, 0, 0, 0, 0>, cudaFuncAttributeMaxDynamicSharedMemorySize, SMEM_BYTES);
    cudaFuncSetAttribute(gemm_mma<0, 1, 1, 0, 1, 0>, cudaFuncAttributeMaxDynamicSharedMemorySize, SMEM_BYTES);

    int MT = E / 128;  // 3125

    k_mask<<<(E + 255) / 256, 256>>>(src, dst, E);
    k_feat<<<(E * 32 + 255) / 256, 256>>>(atom, el, src, dst, E);
    k_angleX<<<(E + 127) / 128, 128>>>(ev, aw1, ab1, ag, abn, E);
    k_split<<<(147456 + 255) / 256, 256>>>(iw1, W + OFF_IW1, 147456);
    k_wtrans<<<(384 * 64 + 255) / 256, 256>>>(iw1, aw2, ab2);
    k_init<<<(Na * 128 + 255) / 256, 256>>>(node, Na * 128);
    k_split<<<(49152 + 255) / 256, 256>>>(iw2, W + OFF_IW2, 49152);
    k_split<<<(40960 + 255) / 256, 256>>>(mw1, W + OFF_MW1, 40960);
    k_split<<<(16384 + 255) / 256, 256>>>(mw2, W + OFF_MW2, 16384);
    // GEMM1: feat @ iw1' + ib1 (+ masked folded angle-b2) -> h1 fp16
    gemm_mma<0, 0, 0, 1, 0, 1><<<dim3(3, MT), 256, SMEM_BYTES>>>(
        A, W + OFF_IW1, ib1, nullptr, 384, 384, nullptr, nullptr, nullptr, h1h,
        nullptr, nullptr, nullptr, nullptr, nullptr, nullptr);
    ln_silu_hh<384><<<(E + 7) / 8, 256>>>(h1h, ig, ibn, B, E);
    // GEMM2: silu(ln(h1)) @ iw2 + ib2, scatter-add into node
    gemm_mma<1, 0, 0, 0, 0, 0><<<dim3(1, MT), 256, SMEM_BYTES>>>(
        B, W + OFF_IW2, ib2, node, 128, 384, dst, nullptr, nullptr, nullptr,
        nullptr, nullptr, nullptr, nullptr, nullptr, nullptr);
    // GEMM3+4 fused: gather cat2 -> @mw1+mb1 -> LN+SiLU (smem) -> @mw2+mb2 -> edge
    gemm_mma<0, 1, 1, 0, 1, 0><<<dim3(1, MT), 256, SMEM_BYTES>>>(
        nullptr, W + OFF_MW1, mb1, nullptr, 128, 320, dst, mg, mbn, nullptr,
        src, el, node, W + OFF_MW2, mb2, edge);
}